// round 16
// baseline (speedup 1.0000x reference)
#include <cuda_runtime.h>
#include <cuda_fp16.h>
#include <cstdint>

// ---------------- problem constants ----------------
#define L_T   16
#define BSZ   8
#define H_    32
#define W_    32
#define U_    128
#define P_    256
#define FRAMES 128
#define SP    (BSZ*H_*W_*P_)      // 2,097,152
#define YS_N  (L_T*BSZ*H_*W_*U_)  // 16,777,216
#define BUS_N (L_T*BSZ*H_*W_*P_)  // 33,554,432
#define U_N   (L_T*BSZ*H_*W_*U_)  // 16,777,216
#define EPS_GN 1e-5f

#define NB_W  589824
#define NC_W  589824

#define HALO_BYTES 87040                    // 340 rows x 256B
#define SMEM_GEMM  (HALO_BYTES + 4*32768)   // 218,112

// ---------------- device scratch (allocation-free) ----------------
__device__ __align__(16) __half g_WBh[NB_W];
__device__ __align__(16) __half g_WCh[NC_W];
__device__ float g_Are[P_];
__device__ float g_Aim[P_];
__device__ __align__(16) __half g_u_h[U_N];
__device__ __align__(16) __half2 g_Bus_hre[BUS_N / 2];
__device__ __align__(16) __half2 g_Bus_him[BUS_N / 2];
__device__ __align__(16) __half g_xh_re[BUS_N];
__device__ __align__(16) __half g_xh_im[BUS_N];
__device__ __align__(16) __half g_ysh[YS_N];
__device__ __align__(16) __half g_ys2h[YS_N];

#define LDMX4(r0, r1, r2, r3, addr) \
    asm volatile("ldmatrix.sync.aligned.m8n8.x4.shared.b16 {%0,%1,%2,%3}, [%4];" \
                 : "=r"(r0), "=r"(r1), "=r"(r2), "=r"(r3) : "r"(addr))

#define MMAH(c, a0, a1, a2, a3, b) asm volatile( \
    "mma.sync.aligned.m16n8k16.row.col.f32.f16.f16.f32 " \
    "{%0,%1,%2,%3},{%4,%5,%6,%7},{%8,%9},{%0,%1,%2,%3};" \
    : "+f"((c)[0]), "+f"((c)[1]), "+f"((c)[2]), "+f"((c)[3]) \
    : "r"(a0), "r"(a1), "r"(a2), "r"(a3), "r"((b).x), "r"((b).y))

#define CP16(dst, src, pred) do { \
    int _sz = (pred) ? 16 : 0; \
    asm volatile("cp.async.cg.shared.global [%0], [%1], 16, %2;" \
                 :: "r"(dst), "l"(src), "r"(_sz)); \
} while (0)

#define CP_COMMIT() asm volatile("cp.async.commit_group;" ::: "memory")
#define CP_WAIT2()  asm volatile("cp.async.wait_group 2;" ::: "memory")
#define CP_WAIT0()  asm volatile("cp.async.wait_group 0;" ::: "memory")

// ---------------- K0: discretization + weight pre-permute + u->half --------
__global__ void k_pre(const float* __restrict__ Lre, const float* __restrict__ Lim,
                      const float* __restrict__ lstep,
                      const float* __restrict__ B_ri, const float* __restrict__ C_ri,
                      const float* __restrict__ u_in) {
    int tid = blockIdx.x * blockDim.x + threadIdx.x;
    if (tid < P_) {
        float st = expf(lstep[tid]);
        g_Are[tid] = fminf(Lre[tid], -1e-4f) * st;
        g_Aim[tid] = Lim[tid] * st;
    }
    if (tid < NB_W) {
        int h = tid & 1, reg = (tid >> 1) & 1, lane = (tid >> 2) & 31;
        int ks = (tid >> 7) & 7, nt = (tid >> 10) & 3, wn = (tid >> 12) & 3;
        int nb = (tid >> 14) & 3, tap = tid >> 16;
        int c = ks * 16 + reg * 8 + (lane & 3) * 2 + h;
        int n = nb * 128 + wn * 32 + nt * 8 + (lane >> 2);
        int plane = n >> 8, p = n & 255;
        float v = B_ri[(((size_t)p * 128 + c) * 9 + tap) * 2 + plane] * expf(lstep[p]);
        g_WBh[tid] = __float2half_rn(v);
    }
    int t2 = tid - NB_W;
    if (t2 >= 0 && t2 < NC_W) {
        int h = t2 & 1, reg = (t2 >> 1) & 1, lane = (t2 >> 2) & 31;
        int ks = (t2 >> 7) & 7, nt = (t2 >> 10) & 3, wn = (t2 >> 12) & 3;
        int rest = t2 >> 14;
        int half = rest / 18, kc = rest % 18;
        int cb = kc / 9, tap = kc % 9;
        int p = cb * 128 + ks * 16 + reg * 8 + (lane & 3) * 2 + h;
        int u = wn * 32 + nt * 8 + (lane >> 2);
        float v = (half == 0)
            ?  2.f * C_ri[(((size_t)u * 256 + p) * 9 + tap) * 2]
            : -2.f * C_ri[(((size_t)u * 256 + p) * 9 + tap) * 2 + 1];
        g_WCh[t2] = __float2half_rn(v);
    }
    if (tid < U_N / 4) {
        float4 v = ((const float4*)u_in)[tid];
        __half2* dst = (__half2*)g_u_h;
        dst[2 * tid]     = __floats2half2_rn(v.x, v.y);
        dst[2 * tid + 1] = __floats2half2_rn(v.z, v.w);
    }
}

// -------- compute macro: A from halo tile (per-tap addressing), W stage s --
#define COMPH(s, ky, kx) do { \
    uint32_t wb = wbase + (s) * 32768; \
    int rr[4]; \
    _Pragma("unroll") \
    for (int mt = 0; mt < 4; mt++) { \
        int m0 = wm * 64 + mt * 16; \
        rr[mt] = ((m0 >> 5) + (ky)) * 34 + (m0 & 31) + (kx) + lrow; \
    } \
    _Pragma("unroll") \
    for (int ks = 0; ks < 8; ks++) { \
        uint2 b[4]; \
        _Pragma("unroll") \
        for (int nt = 0; nt < 4; nt++) { \
            uint32_t waddr = wb + ((((wn * 4 + nt) * 8 + ks) * 32 + lane) << 3); \
            asm volatile("ld.shared.v2.b32 {%0,%1}, [%2];" \
                         : "=r"(b[nt].x), "=r"(b[nt].y) : "r"(waddr)); \
        } \
        _Pragma("unroll") \
        for (int mt = 0; mt < 4; mt++) { \
            uint32_t a0, a1, a2, a3; \
            uint32_t ad = abase + rr[mt] * 256 + \
                          ((ks * 32 + lcol) ^ ((rr[mt] & 7) << 4)); \
            LDMX4(a0, a1, a2, a3, ad); \
            _Pragma("unroll") \
            for (int nt = 0; nt < 4; nt++) MMAH(acc[mt][nt], a0, a1, a2, a3, b[nt]); \
        } \
    } \
} while (0)

// ---------------- GEMM B: Bus(re|im) = u (*) B_bar  (half output) ----------
// grid (2, 4, 128): each CTA loads the halo once and runs 2 N-halves (nb).
__global__ __launch_bounds__(512, 1) void k_gemmB(int dummy) {
    extern __shared__ __align__(16) char smem[];
    int tid = threadIdx.x, lane = tid & 31, wid = tid >> 5;
    int wm = wid >> 2, wn = wid & 3;
    int g8 = lane >> 2, tig = lane & 3;
    int lrow = lane & 15, lcol = lane & 16;
    int nbase = blockIdx.x * 2, slab = blockIdx.y, f = blockIdx.z;
    int y0 = slab * 8;
    uint32_t abase = (uint32_t)__cvta_generic_to_shared(smem);
    uint32_t wbase = abase + HALO_BYTES;

    // halo load once (valid for both nb halves)
    for (int idx = tid; idx < 5440; idx += 512) {
        int r = idx >> 4, c16 = idx & 15;
        int hy = r / 34, hx = r - hy * 34;
        int yy = y0 + hy - 1, xx = hx - 1;
        bool ok = ((unsigned)yy < 32u) && ((unsigned)xx < 32u);
        const __half* src = g_u_h + ((((size_t)f * 32 + yy) * 32 + xx) << 7) + c16 * 8;
        uint32_t dst = abase + r * 256 + ((c16 * 16) ^ ((r & 7) << 4));
        CP16(dst, src, ok);
    }
    CP_COMMIT();

#define ISSUE_WB(s, k, nb) do { \
    const __half* wsrc = g_WBh + (((size_t)(k) * 4 + (nb)) << 14); \
    _Pragma("unroll") \
    for (int q = 0; q < 4; q++) { \
        int idx = q * 512 + tid; \
        CP16(wbase + (s) * 32768 + idx * 16, wsrc + idx * 8, true); \
    } \
} while (0)

    for (int nbi = 0; nbi < 2; nbi++) {
        int nb = nbase + nbi;
        if (nbi) __syncthreads();          // all warps done with W ring of prev half

        float acc[4][4][4];
#pragma unroll
        for (int i = 0; i < 4; i++)
#pragma unroll
            for (int j = 0; j < 4; j++)
#pragma unroll
                for (int e = 0; e < 4; e++) acc[i][j][e] = 0.f;

        ISSUE_WB(0, 0, nb); CP_COMMIT();
        ISSUE_WB(1, 1, nb); CP_COMMIT();
        ISSUE_WB(2, 2, nb); CP_COMMIT();
        ISSUE_WB(3, 3, nb); CP_COMMIT();
        CP_WAIT2();                         // halo + stages 0,1 ready; 2,3 in flight
        __syncthreads();
        for (int p = 0; p < 9; p += 2) {
            COMPH(p & 3, p / 3, p % 3);
            if (p + 1 < 9) COMPH((p + 1) & 3, (p + 1) / 3, (p + 1) % 3);
            if (p + 2 < 9) {
                CP_WAIT0();
                __syncthreads();
                if (p + 4 < 9) { ISSUE_WB((p + 4) & 3, p + 4, nb); CP_COMMIT(); }
                if (p + 5 < 9) { ISSUE_WB((p + 5) & 3, p + 5, nb); CP_COMMIT(); }
            }
        }

        __half* base = (nb < 2) ? (__half*)g_Bus_hre : (__half*)g_Bus_him;
        int ch0 = (nb & 1) * 128 + wn * 32;
#pragma unroll
        for (int mt = 0; mt < 4; mt++) {
            int m1 = wm * 64 + mt * 16 + g8, m2 = m1 + 8;
            size_t pix1 = (((size_t)f * 32 + y0 + (m1 >> 5)) * 32 + (m1 & 31)) * 256;
            size_t pix2 = (((size_t)f * 32 + y0 + (m2 >> 5)) * 32 + (m2 & 31)) * 256;
#pragma unroll
            for (int nt = 0; nt < 4; nt++) {
                int ch = ch0 + nt * 8 + tig * 2;
                *(__half2*)(base + pix1 + ch) = __floats2half2_rn(acc[mt][nt][0], acc[mt][nt][1]);
                *(__half2*)(base + pix2 + ch) = __floats2half2_rn(acc[mt][nt][2], acc[mt][nt][3]);
            }
        }
    }
    (void)dummy;
}

// ---------------- K2: scan — prefetch all 16 levels (MLP), then compute ----
__global__ __launch_bounds__(256) void k_scan(const float* __restrict__ x0,
                                              float* __restrict__ out) {
    int t = blockIdx.x * 256 + threadIdx.x;
    int p0 = (2 * t) & 255;
    float ar0 = g_Are[p0],     ai0 = g_Aim[p0];
    float ar1 = g_Are[p0 + 1], ai1 = g_Aim[p0 + 1];
    float2 xv = ((const float2*)x0)[t];
    float xr0 = xv.x, xi0 = 0.f, xr1 = xv.y, xi1 = 0.f;

    uint32_t brr[L_T], bii[L_T];
    {
        size_t idx = (size_t)t;
#pragma unroll
        for (int l = 0; l < L_T; l++, idx += SP / 2) {
            brr[l] = ((const uint32_t*)g_Bus_hre)[idx];
            bii[l] = ((const uint32_t*)g_Bus_him)[idx];
        }
    }
    size_t idx = (size_t)t;
#pragma unroll
    for (int l = 0; l < L_T; l++, idx += SP / 2) {
        float2 br = __half22float2(*(const __half2*)&brr[l]);
        float2 bi = __half22float2(*(const __half2*)&bii[l]);
        float nr0 = fmaf(ar0, xr0, fmaf(-ai0, xi0, br.x));
        float ni0 = fmaf(ar0, xi0, fmaf( ai0, xr0, bi.x));
        float nr1 = fmaf(ar1, xr1, fmaf(-ai1, xi1, br.y));
        float ni1 = fmaf(ar1, xi1, fmaf( ai1, xr1, bi.y));
        xr0 = nr0; xi0 = ni0; xr1 = nr1; xi1 = ni1;
        ((__half2*)g_xh_re)[idx] = __floats2half2_rn(xr0, xr1);
        ((__half2*)g_xh_im)[idx] = __floats2half2_rn(xi0, xi1);
    }
    ((float4*)out)[t] = make_float4(xr0, xi0, xr1, xi1);
}

// ---------------- GEMM C: ys = 2Re(C (*) x), K-split re/im, half out -------
__global__ __launch_bounds__(512, 1) void k_gemmC(int dummy) {
    extern __shared__ __align__(16) char smem[];
    int tid = threadIdx.x, lane = tid & 31, wid = tid >> 5;
    int wm = wid >> 2, wn = wid & 3;
    int g8 = lane >> 2, tig = lane & 3;
    int lrow = lane & 15, lcol = lane & 16;
    int slab = blockIdx.x, f = blockIdx.y, half = blockIdx.z;
    int y0 = slab * 8;
    const __half* srcb = half ? g_xh_im : g_xh_re;
    uint32_t abase = (uint32_t)__cvta_generic_to_shared(smem);
    uint32_t wbase = abase + HALO_BYTES;

    float acc[4][4][4];
#pragma unroll
    for (int i = 0; i < 4; i++)
#pragma unroll
        for (int j = 0; j < 4; j++)
#pragma unroll
            for (int e = 0; e < 4; e++) acc[i][j][e] = 0.f;

#define ISSUE_HALO_C(cb) do { \
    for (int idx = tid; idx < 5440; idx += 512) { \
        int r = idx >> 4, c16 = idx & 15; \
        int hy = r / 34, hx = r - hy * 34; \
        int yy = y0 + hy - 1, xx = hx - 1; \
        bool ok = ((unsigned)yy < 32u) && ((unsigned)xx < 32u); \
        const __half* src = srcb + ((((size_t)f * 32 + yy) * 32 + xx) << 8) + (cb) * 128 + c16 * 8; \
        uint32_t dst = abase + r * 256 + ((c16 * 16) ^ ((r & 7) << 4)); \
        CP16(dst, src, ok); \
    } \
} while (0)

#define ISSUE_WC(s, c) do { \
    const __half* wsrc = g_WCh + (((size_t)half * 18 + (c)) << 14); \
    _Pragma("unroll") \
    for (int q = 0; q < 4; q++) { \
        int idx = q * 512 + tid; \
        CP16(wbase + (s) * 32768 + idx * 16, wsrc + idx * 8, true); \
    } \
} while (0)

    for (int ph = 0; ph < 2; ph++) {
        if (ph) __syncthreads();
        ISSUE_HALO_C(ph); CP_COMMIT();
#pragma unroll
        for (int j = 0; j < 4; j++) { ISSUE_WC(j, ph * 9 + j); CP_COMMIT(); }
        CP_WAIT2();                         // halo + stages 0,1 ready
        __syncthreads();
        for (int p = 0; p < 9; p += 2) {
            COMPH(p & 3, p / 3, p % 3);
            if (p + 1 < 9) COMPH((p + 1) & 3, (p + 1) / 3, (p + 1) % 3);
            if (p + 2 < 9) {
                CP_WAIT0();
                __syncthreads();
                if (p + 4 < 9) { ISSUE_WC((p + 4) & 3, ph * 9 + p + 4); CP_COMMIT(); }
                if (p + 5 < 9) { ISSUE_WC((p + 5) & 3, ph * 9 + p + 5); CP_COMMIT(); }
            }
        }
    }

    __half* ybase = half ? g_ys2h : g_ysh;
#pragma unroll
    for (int mt = 0; mt < 4; mt++) {
        int m1 = wm * 64 + mt * 16 + g8, m2 = m1 + 8;
        size_t pix1 = (((size_t)f * 32 + y0 + (m1 >> 5)) * 32 + (m1 & 31)) * 128;
        size_t pix2 = (((size_t)f * 32 + y0 + (m2 >> 5)) * 32 + (m2 & 31)) * 128;
#pragma unroll
        for (int nt = 0; nt < 4; nt++) {
            int ch = wn * 32 + nt * 8 + tig * 2;
            *(__half2*)(ybase + pix1 + ch) = __floats2half2_rn(acc[mt][nt][0], acc[mt][nt][1]);
            *(__half2*)(ybase + pix2 + ch) = __floats2half2_rn(acc[mt][nt][2], acc[mt][nt][3]);
        }
    }
    (void)dummy;
}

// ---------------- K4: fused depthwise-D + GroupNorm(32) + GELU -------------
// block = frame, 1024 thr. Thread's 8-ch window (t&15)*8 is iteration-invariant.
// Du recomputed in pass 2 (u frame is L2-resident, 256 KB).
__global__ __launch_bounds__(1024) void k_gn(const float* __restrict__ Dk,
                                             const float* __restrict__ scale,
                                             const float* __restrict__ bias,
                                             float* __restrict__ out) {
    int f = blockIdx.x, t = threadIdx.x;
    size_t cbase = (size_t)f * 16384;
    const uint4* p1 = ((const uint4*)g_ysh) + cbase;
    const uint4* p2 = ((const uint4*)g_ys2h) + cbase;
    const uint4* pu = ((const uint4*)g_u_h) + cbase;
    int chsel = t & 15;
    int ch0 = chsel * 8;
    int gr0 = ch0 >> 2;

    __shared__ float sDk[9 * 128];
    __shared__ float gs[32], gs2[32], gmu[32], grs[32];
    for (int i = t; i < 1152; i += 1024) sDk[i] = Dk[i];
    if (t < 32) { gs[t] = 0.f; gs2[t] = 0.f; }
    __syncthreads();

#define GN_VAL(c, v) do { \
    int _p = (c) >> 4; \
    int _y = _p >> 5, _x = _p & 31; \
    uint4 _a = p1[c]; \
    uint4 _b = p2[c]; \
    const uint32_t* _ap = &_a.x; \
    const uint32_t* _bp = &_b.x; \
    _Pragma("unroll") \
    for (int _j = 0; _j < 4; _j++) { \
        float2 _va = __half22float2(*(const __half2*)&_ap[_j]); \
        float2 _vb = __half22float2(*(const __half2*)&_bp[_j]); \
        (v)[2 * _j]     = _va.x + _vb.x; \
        (v)[2 * _j + 1] = _va.y + _vb.y; \
    } \
    _Pragma("unroll") \
    for (int _ky = 0; _ky < 3; _ky++) { \
        _Pragma("unroll") \
        for (int _kx = 0; _kx < 3; _kx++) { \
            int _yy = _y + _ky - 1, _xx = _x + _kx - 1; \
            if ((unsigned)_yy < 32u && (unsigned)_xx < 32u) { \
                uint4 _uv = pu[(c) + ((_ky - 1) * 32 + (_kx - 1)) * 16]; \
                const uint32_t* _up = &_uv.x; \
                const float* _dkt = sDk + (_ky * 3 + _kx) * 128 + ch0; \
                _Pragma("unroll") \
                for (int _j = 0; _j < 4; _j++) { \
                    float2 _uu = __half22float2(*(const __half2*)&_up[_j]); \
                    (v)[2 * _j]     = fmaf(_uu.x, _dkt[2 * _j],     (v)[2 * _j]); \
                    (v)[2 * _j + 1] = fmaf(_uu.y, _dkt[2 * _j + 1], (v)[2 * _j + 1]); \
                } \
            } \
        } \
    } \
} while (0)

    float s0 = 0.f, s20 = 0.f, s1 = 0.f, s21 = 0.f;
    for (int i = 0; i < 16; i++) {
        int c = i * 1024 + t;
        float v[8];
        GN_VAL(c, v);
#pragma unroll
        for (int j = 0; j < 4; j++) { s0 += v[j]; s20 += v[j] * v[j]; }
#pragma unroll
        for (int j = 4; j < 8; j++) { s1 += v[j]; s21 += v[j] * v[j]; }
    }
    atomicAdd(&gs[gr0], s0);      atomicAdd(&gs2[gr0], s20);
    atomicAdd(&gs[gr0 + 1], s1);  atomicAdd(&gs2[gr0 + 1], s21);
    __syncthreads();
    if (t < 32) {
        float mu = gs[t] * (1.f / 4096.f);
        float var = gs2[t] * (1.f / 4096.f) - mu * mu;
        gmu[t] = mu;
        grs[t] = rsqrtf(var + EPS_GN);
    }
    __syncthreads();

    float mu0 = gmu[gr0], rs0 = grs[gr0];
    float mu1 = gmu[gr0 + 1], rs1 = grs[gr0 + 1];
    float sc[8], bi[8];
#pragma unroll
    for (int j = 0; j < 8; j++) { sc[j] = scale[ch0 + j]; bi[j] = bias[ch0 + j]; }

    float4* outy = (float4*)(out + (size_t)SP * 2 + (size_t)f * (H_ * W_ * U_));
    for (int i = 0; i < 16; i++) {
        int c = i * 1024 + t;
        float v[8];
        GN_VAL(c, v);
        float r[8];
#pragma unroll
        for (int j = 0; j < 8; j++) {
            float mu = (j < 4) ? mu0 : mu1;
            float rsd = (j < 4) ? rs0 : rs1;
            float h = (v[j] - mu) * rsd * sc[j] + bi[j];
            float tt = 0.7978845608028654f * (h + 0.044715f * h * h * h);
            r[j] = 0.5f * h * (1.f + tanhf(tt));
        }
        outy[2 * c]     = make_float4(r[0], r[1], r[2], r[3]);
        outy[2 * c + 1] = make_float4(r[4], r[5], r[6], r[7]);
    }
}

// ---------------- launch ----------------
extern "C" void kernel_launch(void* const* d_in, const int* in_sizes, int n_in,
                              void* d_out, int out_size) {
    const float* u_in  = (const float*)d_in[0];
    const float* x0    = (const float*)d_in[1];
    const float* Lre   = (const float*)d_in[2];
    const float* Lim   = (const float*)d_in[3];
    const float* B_ri  = (const float*)d_in[4];
    const float* C_ri  = (const float*)d_in[5];
    const float* lstep = (const float*)d_in[6];
    const float* Dk    = (const float*)d_in[7];
    const float* gsc   = (const float*)d_in[8];
    const float* gbi   = (const float*)d_in[9];
    float* out = (float*)d_out;
    (void)in_sizes; (void)n_in; (void)out_size;

    cudaFuncSetAttribute(k_gemmB, cudaFuncAttributeMaxDynamicSharedMemorySize, SMEM_GEMM);
    cudaFuncSetAttribute(k_gemmC, cudaFuncAttributeMaxDynamicSharedMemorySize, SMEM_GEMM);

    k_pre<<<(U_N / 4 + 255) / 256, 256>>>(Lre, Lim, lstep, B_ri, C_ri, u_in);
    k_gemmB<<<dim3(2, 4, FRAMES), 512, SMEM_GEMM>>>(0);
    k_scan<<<SP / 2 / 256, 256>>>(x0, out);
    k_gemmC<<<dim3(4, FRAMES, 2), 512, SMEM_GEMM>>>(0);
    k_gn<<<FRAMES, 1024>>>(Dk, gsc, gbi, out);
}

// round 17
// speedup vs baseline: 1.0428x; 1.0428x over previous
#include <cuda_runtime.h>
#include <cuda_fp16.h>
#include <cstdint>

// ---------------- problem constants ----------------
#define L_T   16
#define BSZ   8
#define H_    32
#define W_    32
#define U_    128
#define P_    256
#define FRAMES 128
#define SP    (BSZ*H_*W_*P_)      // 2,097,152
#define YS_N  (L_T*BSZ*H_*W_*U_)  // 16,777,216
#define BUS_N (L_T*BSZ*H_*W_*P_)  // 33,554,432
#define U_N   (L_T*BSZ*H_*W_*U_)  // 16,777,216
#define EPS_GN 1e-5f

#define NB_W  589824
#define NC_W  589824

#define HALO_BYTES 87040                    // 340 rows x 256B
#define SMEM_GEMM  (HALO_BYTES + 4*32768)   // 218,112

// ---------------- device scratch (allocation-free) ----------------
__device__ __align__(16) __half g_WBh[NB_W];
__device__ __align__(16) __half g_WCh[NC_W];
__device__ float g_Are[P_];
__device__ float g_Aim[P_];
__device__ __align__(16) __half g_u_h[U_N];
__device__ __align__(16) __half2 g_Bus_hre[BUS_N / 2];
__device__ __align__(16) __half2 g_Bus_him[BUS_N / 2];
__device__ __align__(16) __half g_xh_re[BUS_N];
__device__ __align__(16) __half g_xh_im[BUS_N];
__device__ __align__(16) __half g_ysh[YS_N];
__device__ __align__(16) __half g_ys2h[YS_N];

#define LDMX4(r0, r1, r2, r3, addr) \
    asm volatile("ldmatrix.sync.aligned.m8n8.x4.shared.b16 {%0,%1,%2,%3}, [%4];" \
                 : "=r"(r0), "=r"(r1), "=r"(r2), "=r"(r3) : "r"(addr))

#define MMAH(c, a0, a1, a2, a3, b) asm volatile( \
    "mma.sync.aligned.m16n8k16.row.col.f32.f16.f16.f32 " \
    "{%0,%1,%2,%3},{%4,%5,%6,%7},{%8,%9},{%0,%1,%2,%3};" \
    : "+f"((c)[0]), "+f"((c)[1]), "+f"((c)[2]), "+f"((c)[3]) \
    : "r"(a0), "r"(a1), "r"(a2), "r"(a3), "r"((b).x), "r"((b).y))

#define CP16(dst, src, pred) do { \
    int _sz = (pred) ? 16 : 0; \
    asm volatile("cp.async.cg.shared.global [%0], [%1], 16, %2;" \
                 :: "r"(dst), "l"(src), "r"(_sz)); \
} while (0)

#define CP_COMMIT() asm volatile("cp.async.commit_group;" ::: "memory")
#define CP_WAIT2()  asm volatile("cp.async.wait_group 2;" ::: "memory")
#define CP_WAIT0()  asm volatile("cp.async.wait_group 0;" ::: "memory")

// ---------------- K0: discretization + weight pre-permute + u->half --------
__global__ void k_pre(const float* __restrict__ Lre, const float* __restrict__ Lim,
                      const float* __restrict__ lstep,
                      const float* __restrict__ B_ri, const float* __restrict__ C_ri,
                      const float* __restrict__ u_in) {
    int tid = blockIdx.x * blockDim.x + threadIdx.x;
    if (tid < P_) {
        float st = expf(lstep[tid]);
        g_Are[tid] = fminf(Lre[tid], -1e-4f) * st;
        g_Aim[tid] = Lim[tid] * st;
    }
    if (tid < NB_W) {
        int h = tid & 1, reg = (tid >> 1) & 1, lane = (tid >> 2) & 31;
        int ks = (tid >> 7) & 7, nt = (tid >> 10) & 3, wn = (tid >> 12) & 3;
        int nb = (tid >> 14) & 3, tap = tid >> 16;
        int c = ks * 16 + reg * 8 + (lane & 3) * 2 + h;
        int n = nb * 128 + wn * 32 + nt * 8 + (lane >> 2);
        int plane = n >> 8, p = n & 255;
        float v = B_ri[(((size_t)p * 128 + c) * 9 + tap) * 2 + plane] * expf(lstep[p]);
        g_WBh[tid] = __float2half_rn(v);
    }
    int t2 = tid - NB_W;
    if (t2 >= 0 && t2 < NC_W) {
        int h = t2 & 1, reg = (t2 >> 1) & 1, lane = (t2 >> 2) & 31;
        int ks = (t2 >> 7) & 7, nt = (t2 >> 10) & 3, wn = (t2 >> 12) & 3;
        int rest = t2 >> 14;
        int half = rest / 18, kc = rest % 18;
        int cb = kc / 9, tap = kc % 9;
        int p = cb * 128 + ks * 16 + reg * 8 + (lane & 3) * 2 + h;
        int u = wn * 32 + nt * 8 + (lane >> 2);
        float v = (half == 0)
            ?  2.f * C_ri[(((size_t)u * 256 + p) * 9 + tap) * 2]
            : -2.f * C_ri[(((size_t)u * 256 + p) * 9 + tap) * 2 + 1];
        g_WCh[t2] = __float2half_rn(v);
    }
    if (tid < U_N / 4) {
        float4 v = ((const float4*)u_in)[tid];
        __half2* dst = (__half2*)g_u_h;
        dst[2 * tid]     = __floats2half2_rn(v.x, v.y);
        dst[2 * tid + 1] = __floats2half2_rn(v.z, v.w);
    }
}

// -------- compute macro: A from halo tile (per-tap addressing), W stage s --
#define COMPH(s, ky, kx) do { \
    uint32_t wb = wbase + (s) * 32768; \
    int rr[4]; \
    _Pragma("unroll") \
    for (int mt = 0; mt < 4; mt++) { \
        int m0 = wm * 64 + mt * 16; \
        rr[mt] = ((m0 >> 5) + (ky)) * 34 + (m0 & 31) + (kx) + lrow; \
    } \
    _Pragma("unroll") \
    for (int ks = 0; ks < 8; ks++) { \
        uint2 b[4]; \
        _Pragma("unroll") \
        for (int nt = 0; nt < 4; nt++) { \
            uint32_t waddr = wb + ((((wn * 4 + nt) * 8 + ks) * 32 + lane) << 3); \
            asm volatile("ld.shared.v2.b32 {%0,%1}, [%2];" \
                         : "=r"(b[nt].x), "=r"(b[nt].y) : "r"(waddr)); \
        } \
        _Pragma("unroll") \
        for (int mt = 0; mt < 4; mt++) { \
            uint32_t a0, a1, a2, a3; \
            uint32_t ad = abase + rr[mt] * 256 + \
                          ((ks * 32 + lcol) ^ ((rr[mt] & 7) << 4)); \
            LDMX4(a0, a1, a2, a3, ad); \
            _Pragma("unroll") \
            for (int nt = 0; nt < 4; nt++) MMAH(acc[mt][nt], a0, a1, a2, a3, b[nt]); \
        } \
    } \
} while (0)

// ---------------- GEMM B: Bus(re|im) = u (*) B_bar  (half output) ----------
// grid (2, 4, 128): each CTA loads the halo once and runs 2 N-halves (nb).
__global__ __launch_bounds__(512, 1) void k_gemmB(int dummy) {
    extern __shared__ __align__(16) char smem[];
    int tid = threadIdx.x, lane = tid & 31, wid = tid >> 5;
    int wm = wid >> 2, wn = wid & 3;
    int g8 = lane >> 2, tig = lane & 3;
    int lrow = lane & 15, lcol = lane & 16;
    int nbase = blockIdx.x * 2, slab = blockIdx.y, f = blockIdx.z;
    int y0 = slab * 8;
    uint32_t abase = (uint32_t)__cvta_generic_to_shared(smem);
    uint32_t wbase = abase + HALO_BYTES;

    // halo load once (valid for both nb halves)
    for (int idx = tid; idx < 5440; idx += 512) {
        int r = idx >> 4, c16 = idx & 15;
        int hy = r / 34, hx = r - hy * 34;
        int yy = y0 + hy - 1, xx = hx - 1;
        bool ok = ((unsigned)yy < 32u) && ((unsigned)xx < 32u);
        const __half* src = g_u_h + ((((size_t)f * 32 + yy) * 32 + xx) << 7) + c16 * 8;
        uint32_t dst = abase + r * 256 + ((c16 * 16) ^ ((r & 7) << 4));
        CP16(dst, src, ok);
    }
    CP_COMMIT();

#define ISSUE_WB(s, k, nb) do { \
    const __half* wsrc = g_WBh + (((size_t)(k) * 4 + (nb)) << 14); \
    _Pragma("unroll") \
    for (int q = 0; q < 4; q++) { \
        int idx = q * 512 + tid; \
        CP16(wbase + (s) * 32768 + idx * 16, wsrc + idx * 8, true); \
    } \
} while (0)

    for (int nbi = 0; nbi < 2; nbi++) {
        int nb = nbase + nbi;
        if (nbi) __syncthreads();          // all warps done with W ring of prev half

        float acc[4][4][4];
#pragma unroll
        for (int i = 0; i < 4; i++)
#pragma unroll
            for (int j = 0; j < 4; j++)
#pragma unroll
                for (int e = 0; e < 4; e++) acc[i][j][e] = 0.f;

        ISSUE_WB(0, 0, nb); CP_COMMIT();
        ISSUE_WB(1, 1, nb); CP_COMMIT();
        ISSUE_WB(2, 2, nb); CP_COMMIT();
        ISSUE_WB(3, 3, nb); CP_COMMIT();
        CP_WAIT2();                         // halo + stages 0,1 ready; 2,3 in flight
        __syncthreads();
        for (int p = 0; p < 9; p += 2) {
            COMPH(p & 3, p / 3, p % 3);
            if (p + 1 < 9) COMPH((p + 1) & 3, (p + 1) / 3, (p + 1) % 3);
            if (p + 2 < 9) {
                CP_WAIT0();
                __syncthreads();
                if (p + 4 < 9) { ISSUE_WB((p + 4) & 3, p + 4, nb); CP_COMMIT(); }
                if (p + 5 < 9) { ISSUE_WB((p + 5) & 3, p + 5, nb); CP_COMMIT(); }
            }
        }

        __half* base = (nb < 2) ? (__half*)g_Bus_hre : (__half*)g_Bus_him;
        int ch0 = (nb & 1) * 128 + wn * 32;
#pragma unroll
        for (int mt = 0; mt < 4; mt++) {
            int m1 = wm * 64 + mt * 16 + g8, m2 = m1 + 8;
            size_t pix1 = (((size_t)f * 32 + y0 + (m1 >> 5)) * 32 + (m1 & 31)) * 256;
            size_t pix2 = (((size_t)f * 32 + y0 + (m2 >> 5)) * 32 + (m2 & 31)) * 256;
#pragma unroll
            for (int nt = 0; nt < 4; nt++) {
                int ch = ch0 + nt * 8 + tig * 2;
                *(__half2*)(base + pix1 + ch) = __floats2half2_rn(acc[mt][nt][0], acc[mt][nt][1]);
                *(__half2*)(base + pix2 + ch) = __floats2half2_rn(acc[mt][nt][2], acc[mt][nt][3]);
            }
        }
    }
    (void)dummy;
}

// ---------------- K2: scan — prefetch all 16 levels (MLP), then compute ----
__global__ __launch_bounds__(256) void k_scan(const float* __restrict__ x0,
                                              float* __restrict__ out) {
    int t = blockIdx.x * 256 + threadIdx.x;
    int p0 = (2 * t) & 255;
    float ar0 = g_Are[p0],     ai0 = g_Aim[p0];
    float ar1 = g_Are[p0 + 1], ai1 = g_Aim[p0 + 1];
    float2 xv = ((const float2*)x0)[t];
    float xr0 = xv.x, xi0 = 0.f, xr1 = xv.y, xi1 = 0.f;

    uint32_t brr[L_T], bii[L_T];
    {
        size_t idx = (size_t)t;
#pragma unroll
        for (int l = 0; l < L_T; l++, idx += SP / 2) {
            brr[l] = ((const uint32_t*)g_Bus_hre)[idx];
            bii[l] = ((const uint32_t*)g_Bus_him)[idx];
        }
    }
    size_t idx = (size_t)t;
#pragma unroll
    for (int l = 0; l < L_T; l++, idx += SP / 2) {
        float2 br = __half22float2(*(const __half2*)&brr[l]);
        float2 bi = __half22float2(*(const __half2*)&bii[l]);
        float nr0 = fmaf(ar0, xr0, fmaf(-ai0, xi0, br.x));
        float ni0 = fmaf(ar0, xi0, fmaf( ai0, xr0, bi.x));
        float nr1 = fmaf(ar1, xr1, fmaf(-ai1, xi1, br.y));
        float ni1 = fmaf(ar1, xi1, fmaf( ai1, xr1, bi.y));
        xr0 = nr0; xi0 = ni0; xr1 = nr1; xi1 = ni1;
        ((__half2*)g_xh_re)[idx] = __floats2half2_rn(xr0, xr1);
        ((__half2*)g_xh_im)[idx] = __floats2half2_rn(xi0, xi1);
    }
    ((float4*)out)[t] = make_float4(xr0, xi0, xr1, xi1);
}

// ---------------- GEMM C: ys = 2Re(C (*) x), K-split re/im, half out -------
__global__ __launch_bounds__(512, 1) void k_gemmC(int dummy) {
    extern __shared__ __align__(16) char smem[];
    int tid = threadIdx.x, lane = tid & 31, wid = tid >> 5;
    int wm = wid >> 2, wn = wid & 3;
    int g8 = lane >> 2, tig = lane & 3;
    int lrow = lane & 15, lcol = lane & 16;
    int slab = blockIdx.x, f = blockIdx.y, half = blockIdx.z;
    int y0 = slab * 8;
    const __half* srcb = half ? g_xh_im : g_xh_re;
    uint32_t abase = (uint32_t)__cvta_generic_to_shared(smem);
    uint32_t wbase = abase + HALO_BYTES;

    float acc[4][4][4];
#pragma unroll
    for (int i = 0; i < 4; i++)
#pragma unroll
        for (int j = 0; j < 4; j++)
#pragma unroll
            for (int e = 0; e < 4; e++) acc[i][j][e] = 0.f;

#define ISSUE_HALO_C(cb) do { \
    for (int idx = tid; idx < 5440; idx += 512) { \
        int r = idx >> 4, c16 = idx & 15; \
        int hy = r / 34, hx = r - hy * 34; \
        int yy = y0 + hy - 1, xx = hx - 1; \
        bool ok = ((unsigned)yy < 32u) && ((unsigned)xx < 32u); \
        const __half* src = srcb + ((((size_t)f * 32 + yy) * 32 + xx) << 8) + (cb) * 128 + c16 * 8; \
        uint32_t dst = abase + r * 256 + ((c16 * 16) ^ ((r & 7) << 4)); \
        CP16(dst, src, ok); \
    } \
} while (0)

#define ISSUE_WC(s, c) do { \
    const __half* wsrc = g_WCh + (((size_t)half * 18 + (c)) << 14); \
    _Pragma("unroll") \
    for (int q = 0; q < 4; q++) { \
        int idx = q * 512 + tid; \
        CP16(wbase + (s) * 32768 + idx * 16, wsrc + idx * 8, true); \
    } \
} while (0)

    for (int ph = 0; ph < 2; ph++) {
        if (ph) __syncthreads();
        ISSUE_HALO_C(ph); CP_COMMIT();
#pragma unroll
        for (int j = 0; j < 4; j++) { ISSUE_WC(j, ph * 9 + j); CP_COMMIT(); }
        CP_WAIT2();                         // halo + stages 0,1 ready
        __syncthreads();
        for (int p = 0; p < 9; p += 2) {
            COMPH(p & 3, p / 3, p % 3);
            if (p + 1 < 9) COMPH((p + 1) & 3, (p + 1) / 3, (p + 1) % 3);
            if (p + 2 < 9) {
                CP_WAIT0();
                __syncthreads();
                if (p + 4 < 9) { ISSUE_WC((p + 4) & 3, ph * 9 + p + 4); CP_COMMIT(); }
                if (p + 5 < 9) { ISSUE_WC((p + 5) & 3, ph * 9 + p + 5); CP_COMMIT(); }
            }
        }
    }

    __half* ybase = half ? g_ys2h : g_ysh;
#pragma unroll
    for (int mt = 0; mt < 4; mt++) {
        int m1 = wm * 64 + mt * 16 + g8, m2 = m1 + 8;
        size_t pix1 = (((size_t)f * 32 + y0 + (m1 >> 5)) * 32 + (m1 & 31)) * 128;
        size_t pix2 = (((size_t)f * 32 + y0 + (m2 >> 5)) * 32 + (m2 & 31)) * 128;
#pragma unroll
        for (int nt = 0; nt < 4; nt++) {
            int ch = wn * 32 + nt * 8 + tig * 2;
            *(__half2*)(ybase + pix1 + ch) = __floats2half2_rn(acc[mt][nt][0], acc[mt][nt][1]);
            *(__half2*)(ybase + pix2 + ch) = __floats2half2_rn(acc[mt][nt][2], acc[mt][nt][3]);
        }
    }
    (void)dummy;
}

// ---------------- K3b: depthwise D feedthrough (half u in, += half ys) -----
__global__ __launch_bounds__(128) void k_dw(const float* __restrict__ Dk) {
    int f = blockIdx.x, y = blockIdx.y, u = threadIdx.x;
    float dk[9];
#pragma unroll
    for (int j = 0; j < 9; j++) dk[j] = Dk[j * U_ + u];
    float acc[W_];
#pragma unroll
    for (int x = 0; x < W_; x++) acc[x] = 0.f;
    for (int ky = 0; ky < 3; ky++) {
        int yi = y + ky - 1;
        if (yi < 0 || yi >= H_) continue;
        const __half* row = g_u_h + ((size_t)(f * H_ + yi) * W_) * U_ + u;
        float v0 = 0.f, v1 = __half2float(row[0]);
#pragma unroll
        for (int x = 0; x < W_; x++) {
            float v2 = (x + 1 < W_) ? __half2float(row[(x + 1) * U_]) : 0.f;
            acc[x] = fmaf(v0, dk[ky * 3], fmaf(v1, dk[ky * 3 + 1], fmaf(v2, dk[ky * 3 + 2], acc[x])));
            v0 = v1; v1 = v2;
        }
    }
    size_t base = ((size_t)(f * H_ + y) * W_) * U_ + u;
#pragma unroll
    for (int x = 0; x < W_; x++) {
        size_t idx = base + (size_t)x * U_;
        g_ysh[idx] = __float2half_rn(__half2float(g_ysh[idx]) + acc[x]);
    }
}

// ---------------- K4: GroupNorm(32) + GELU, coalesced (block = frame) ------
__global__ __launch_bounds__(512) void k_gn(const float* __restrict__ scale,
                                            const float* __restrict__ bias,
                                            float* __restrict__ out) {
    int f = blockIdx.x, t = threadIdx.x;
    size_t cbase = (size_t)f * 16384;
    const uint4* p1 = ((const uint4*)g_ysh) + cbase;
    const uint4* p2 = ((const uint4*)g_ys2h) + cbase;
    int ch0 = (t * 8) & 127;
    int gr0 = ch0 >> 2;

    __shared__ float gs[32], gs2[32], gmu[32], grs[32];
    if (t < 32) { gs[t] = 0.f; gs2[t] = 0.f; }
    __syncthreads();

    float s0 = 0.f, s20 = 0.f, s1 = 0.f, s21 = 0.f;
    for (int i = 0; i < 32; i++) {
        int c = i * 512 + t;
        uint4 a = p1[c];
        uint4 b = p2[c];
        const uint32_t* ap = &a.x;
        const uint32_t* bp = &b.x;
#pragma unroll
        for (int j = 0; j < 4; j++) {
            float2 va = __half22float2(*(const __half2*)&ap[j]);
            float2 vb = __half22float2(*(const __half2*)&bp[j]);
            float v0 = va.x + vb.x, v1 = va.y + vb.y;
            if (j < 2) { s0 += v0 + v1; s20 += v0 * v0 + v1 * v1; }
            else       { s1 += v0 + v1; s21 += v0 * v0 + v1 * v1; }
        }
    }
    atomicAdd(&gs[gr0], s0);  atomicAdd(&gs2[gr0], s20);
    atomicAdd(&gs[gr0 + 1], s1); atomicAdd(&gs2[gr0 + 1], s21);
    __syncthreads();
    if (t < 32) {
        float mu = gs[t] * (1.f / 4096.f);
        float var = gs2[t] * (1.f / 4096.f) - mu * mu;
        gmu[t] = mu;
        grs[t] = rsqrtf(var + EPS_GN);
    }
    __syncthreads();

    float mu0 = gmu[gr0], rs0 = grs[gr0];
    float mu1 = gmu[gr0 + 1], rs1 = grs[gr0 + 1];
    float sc[8], bi[8];
#pragma unroll
    for (int j = 0; j < 8; j++) { sc[j] = scale[ch0 + j]; bi[j] = bias[ch0 + j]; }

    float4* outy = (float4*)(out + (size_t)SP * 2 + (size_t)f * (H_ * W_ * U_));
    for (int i = 0; i < 32; i++) {
        int c = i * 512 + t;
        uint4 a = p1[c];
        uint4 b = p2[c];
        const uint32_t* ap = &a.x;
        const uint32_t* bp = &b.x;
        float r[8];
#pragma unroll
        for (int j = 0; j < 4; j++) {
            float2 va = __half22float2(*(const __half2*)&ap[j]);
            float2 vb = __half22float2(*(const __half2*)&bp[j]);
            float mu = (j < 2) ? mu0 : mu1;
            float rsd = (j < 2) ? rs0 : rs1;
            float v0 = va.x + vb.x, v1 = va.y + vb.y;
            float h0 = (v0 - mu) * rsd * sc[2 * j] + bi[2 * j];
            float h1 = (v1 - mu) * rsd * sc[2 * j + 1] + bi[2 * j + 1];
            float t0 = 0.7978845608028654f * (h0 + 0.044715f * h0 * h0 * h0);
            float t1 = 0.7978845608028654f * (h1 + 0.044715f * h1 * h1 * h1);
            r[2 * j]     = 0.5f * h0 * (1.f + tanhf(t0));
            r[2 * j + 1] = 0.5f * h1 * (1.f + tanhf(t1));
        }
        outy[2 * c]     = make_float4(r[0], r[1], r[2], r[3]);
        outy[2 * c + 1] = make_float4(r[4], r[5], r[6], r[7]);
    }
}

// ---------------- launch ----------------
extern "C" void kernel_launch(void* const* d_in, const int* in_sizes, int n_in,
                              void* d_out, int out_size) {
    const float* u_in  = (const float*)d_in[0];
    const float* x0    = (const float*)d_in[1];
    const float* Lre   = (const float*)d_in[2];
    const float* Lim   = (const float*)d_in[3];
    const float* B_ri  = (const float*)d_in[4];
    const float* C_ri  = (const float*)d_in[5];
    const float* lstep = (const float*)d_in[6];
    const float* Dk    = (const float*)d_in[7];
    const float* gsc   = (const float*)d_in[8];
    const float* gbi   = (const float*)d_in[9];
    float* out = (float*)d_out;
    (void)in_sizes; (void)n_in; (void)out_size;

    cudaFuncSetAttribute(k_gemmB, cudaFuncAttributeMaxDynamicSharedMemorySize, SMEM_GEMM);
    cudaFuncSetAttribute(k_gemmC, cudaFuncAttributeMaxDynamicSharedMemorySize, SMEM_GEMM);

    k_pre<<<(U_N / 4 + 255) / 256, 256>>>(Lre, Lim, lstep, B_ri, C_ri, u_in);
    k_gemmB<<<dim3(2, 4, FRAMES), 512, SMEM_GEMM>>>(0);
    k_scan<<<SP / 2 / 256, 256>>>(x0, out);
    k_gemmC<<<dim3(4, FRAMES, 2), 512, SMEM_GEMM>>>(0);
    k_dw<<<dim3(FRAMES, H_), 128>>>(Dk);
    k_gn<<<FRAMES, 512>>>(gsc, gbi, out);
}